// round 16
// baseline (speedup 1.0000x reference)
#include <cuda_runtime.h>
#include <cstddef>

// Fixed shapes
#define T_STEPS 336
#define NT      256          // 8 warps: 4 producer (L0), 4 consumer (L1)
#define NCTAS   128          // 8 batch elems per CTA

typedef unsigned long long u64;

// ---- shared memory layout (float offsets) ----
// Weights: per k-pair row (stride WS=520):
//   [0..255]   if-plane: j*4 + {Wi_k, Wi_k1, Wf_k, Wf_k1}
//   [256..511] go-plane: j*4 + {Wg_k, Wg_k1, Wo_k, Wo_k1}
// rows = plain k-pair index (no split-K interleave).
#define WS      520
#define OFF_W0X 0            // 8 rows
#define OFF_W0H 4160         // 32 rows
#define OFF_W1X 20800        // 32 rows
#define OFF_W1H 37440        // 32 rows
#define OFF_B   54080        // 512: [layer*256 + gate*64 + j]
#define OFF_XR  54592        // x ring  [2][8 elems][16]
#define OFF_H0R 54848        // h0 ring [2][8 elems][64]
#define OFF_H1R 55872        // h1 ring [2][8 elems][64]
#define SMEM_FLOATS 56896
#define SMEM_BYTES (SMEM_FLOATS * 4)   // 227,584 B < 232,448 cap

#define BAR_SYNC(id)   asm volatile("bar.sync %0, %1;"   :: "r"(id), "r"(128) : "memory")
#define BAR_ARRIVE(id) asm volatile("bar.arrive %0, %1;" :: "r"(id), "r"(128) : "memory")
#define BAR_PAIR(id)   asm volatile("bar.sync %0, %1;"   :: "r"(id), "r"(64)  : "memory")

// ---- packed helpers ----
__device__ __forceinline__ u64 fma2(u64 a, u64 b, u64 c) {
    u64 d;
    asm("fma.rn.f32x2 %0, %1, %2, %3;" : "=l"(d) : "l"(a), "l"(b), "l"(c));
    return d;
}
__device__ __forceinline__ ulonglong2 lds2(const float* p) {
    return *reinterpret_cast<const ulonglong2*>(p);
}
__device__ __forceinline__ float foldadd(u64 v) {
    float lo, hi;
    asm("mov.b64 {%0,%1}, %2;" : "=f"(lo), "=f"(hi) : "l"(v));
    return lo + hi;
}
__device__ __forceinline__ float sigf(float x) {
    return __fdividef(1.0f, 1.0f + __expf(-x));
}
__device__ __forceinline__ float tanhe(float x) {
    return 1.0f - __fdividef(2.0f, __expf(2.0f * x) + 1.0f);
}

// GEMM over NCH chunks of 4 k (= 2 k-pairs), full-K lanes (no split).
// acc[gate*4+e]. wbase includes j*4. hbase includes e0*HS; per-elem stride HS.
// h loads are warp-wide broadcasts (all lanes same address).
template<int NCH, int HS>
__device__ __forceinline__ void gemm2(u64* __restrict__ acc,
                                      const float* __restrict__ wbase,
                                      const float* __restrict__ hbase)
{
#pragma unroll
    for (int c = 0; c < NCH; ++c) {
        ulonglong2 hv0 = lds2(hbase + 0 * HS + c * 4);
        ulonglong2 hv1 = lds2(hbase + 1 * HS + c * 4);
        ulonglong2 hv2 = lds2(hbase + 2 * HS + c * 4);
        ulonglong2 hv3 = lds2(hbase + 3 * HS + c * 4);
#pragma unroll
        for (int ki2 = 0; ki2 < 2; ++ki2) {
            const float* wr = wbase + (size_t)(2 * c + ki2) * WS;
            const ulonglong2 wif = lds2(wr);
            const ulonglong2 wgo = lds2(wr + 256);
            const u64 h0 = ki2 ? hv0.y : hv0.x;
            const u64 h1 = ki2 ? hv1.y : hv1.x;
            const u64 h2 = ki2 ? hv2.y : hv2.x;
            const u64 h3 = ki2 ? hv3.y : hv3.x;
            acc[0]  = fma2(wif.x, h0, acc[0]);
            acc[1]  = fma2(wif.x, h1, acc[1]);
            acc[2]  = fma2(wif.x, h2, acc[2]);
            acc[3]  = fma2(wif.x, h3, acc[3]);
            acc[4]  = fma2(wif.y, h0, acc[4]);
            acc[5]  = fma2(wif.y, h1, acc[5]);
            acc[6]  = fma2(wif.y, h2, acc[6]);
            acc[7]  = fma2(wif.y, h3, acc[7]);
            acc[8]  = fma2(wgo.x, h0, acc[8]);
            acc[9]  = fma2(wgo.x, h1, acc[9]);
            acc[10] = fma2(wgo.x, h2, acc[10]);
            acc[11] = fma2(wgo.x, h3, acc[11]);
            acc[12] = fma2(wgo.y, h0, acc[12]);
            acc[13] = fma2(wgo.y, h1, acc[13]);
            acc[14] = fma2(wgo.y, h2, acc[14]);
            acc[15] = fma2(wgo.y, h3, acc[15]);
        }
    }
}

__global__ void __launch_bounds__(NT, 1)
lstm2_kernel(const float* __restrict__ x,
             const float* __restrict__ Wih0, const float* __restrict__ Whh0,
             const float* __restrict__ bih0, const float* __restrict__ bhh0,
             const float* __restrict__ Wih1, const float* __restrict__ Whh1,
             const float* __restrict__ bih1, const float* __restrict__ bhh1,
             const float* __restrict__ Wfc,  const float* __restrict__ bfc,
             float* __restrict__ out)
{
    extern __shared__ float sh[];
    const int tid = threadIdx.x;

    // ---- stage weights (rows = plain k-pair index) ----
    for (int idx = tid; idx < 256 * 16; idx += NT) {
        const int gr = idx >> 4, k = idx & 15;
        const int g = gr >> 6, j = gr & 63;
        sh[OFF_W0X + (k >> 1) * WS + (g >> 1) * 256 + j * 4 + (g & 1) * 2 + (k & 1)]
            = Wih0[idx];
    }
    for (int idx = tid; idx < 256 * 64; idx += NT) {
        const int gr = idx >> 6, k = idx & 63;
        const int g = gr >> 6, j = gr & 63;
        const int o = (k >> 1) * WS + (g >> 1) * 256 + j * 4 + (g & 1) * 2 + (k & 1);
        sh[OFF_W0H + o] = Whh0[idx];
        sh[OFF_W1X + o] = Wih1[idx];
        sh[OFF_W1H + o] = Whh1[idx];
    }
    if (tid < 256) {
        sh[OFF_B + tid]       = bih0[tid] + bhh0[tid];
        sh[OFF_B + 256 + tid] = bih1[tid] + bhh1[tid];
    }
    // zero x/h rings (256 + 1024 + 1024 floats)
    for (int idx = tid; idx < 2304; idx += NT) sh[OFF_XR + idx] = 0.0f;

    // ---- thread mapping ----
    // role = wid>>2 (0 = L0 producer, 1 = L1 consumer); group g = wid&1; j-half = (wid>>1)&1
    // SMSP k gets wid k (L0) + wid k+4 (L1) -> fma balanced per SMSP.
    const int wid  = tid >> 5, lane = tid & 31;
    const int role = wid >> 2;
    const int g    = wid & 1;
    const int jh   = (wid >> 1) & 1;
    const int j    = jh * 32 + lane;
    const int e0   = g * 4;
    const int base = 1 + g * 6;          // barrier ids: FULL=base+s, EMPTY=base+2+s,
                                         // L0INT=base+4, L1INT=base+5

    // x staging (producers only): 64 lanes per group -> (elem, k)
    const int l64 = jh * 32 + lane;
    const int xe = l64 >> 4, xk = l64 & 15;
    const float* xptr = x + ((size_t)(blockIdx.x * 8 + e0 + xe) * T_STEPS) * 16 + xk;
    float xreg = 0.0f;
    if (role == 0) {
        sh[OFF_XR + 0 * 128 + (e0 + xe) * 16 + xk] = xptr[0];   // x(0) -> slot 0
        xreg = xptr[16];                                        // prefetch x(1)
    }
    __syncthreads();

    if (role == 0) {
        // ================= Producer: layer-0 recurrence =================
        const float bi = sh[OFF_B +   0 + j], bf = sh[OFF_B +  64 + j];
        const float bg = sh[OFF_B + 128 + j], bo = sh[OFF_B + 192 + j];
        const float* wx = &sh[OFF_W0X + j * 4];
        const float* wh = &sh[OFF_W0H + j * 4];
        float c0[4] = {0.f, 0.f, 0.f, 0.f};

        for (int t = 0; t < T_STEPS; ++t) {
            const int s = t & 1;
            u64 acc[16];
#pragma unroll
            for (int i = 0; i < 16; ++i) acc[i] = 0ull;
            gemm2<4, 16>(acc, wx, &sh[OFF_XR + s * 128 + e0 * 16]);          // x(t)
            gemm2<16, 64>(acc, wh, &sh[OFF_H0R + (1 - s) * 512 + e0 * 64]);  // h0(t-1)

            float hn[4];
#pragma unroll
            for (int e = 0; e < 4; ++e) {
                const float gi = sigf(foldadd(acc[e])      + bi);
                const float gf = sigf(foldadd(acc[4 + e])  + bf);
                const float gg = tanhe(foldadd(acc[8 + e]) + bg);
                const float go = sigf(foldadd(acc[12 + e]) + bo);
                c0[e] = fmaf(gf, c0[e], gi * gg);
                hn[e] = go * tanhe(c0[e]);
            }

            if (t >= 2) BAR_SYNC(base + 2 + s);      // EMPTY[s]: consumers freed h0(t-2)
#pragma unroll
            for (int e = 0; e < 4; ++e)
                sh[OFF_H0R + s * 512 + (e0 + e) * 64 + j] = hn[e];           // h0(t)
            if (t + 1 < T_STEPS)
                sh[OFF_XR + (1 - s) * 128 + (e0 + xe) * 16 + xk] = xreg;     // x(t+1)
            if (t + 2 < T_STEPS)
                xreg = xptr[(size_t)(t + 2) * 16];
            BAR_ARRIVE(base + s);                    // FULL[s]: h0(t) published
            BAR_PAIR(base + 4);                      // L0 pair: h0(t)/x(t+1) visible
        }
    } else {
        // ================= Consumer: layer-1 recurrence =================
        const float bi = sh[OFF_B + 256 + j], bf = sh[OFF_B + 320 + j];
        const float bg = sh[OFF_B + 384 + j], bo = sh[OFF_B + 448 + j];
        const float* wx = &sh[OFF_W1X + j * 4];
        const float* wh = &sh[OFF_W1H + j * 4];
        float c1[4] = {0.f, 0.f, 0.f, 0.f};

        for (int t = 0; t < T_STEPS; ++t) {
            const int s = t & 1;
            u64 acc[16];
#pragma unroll
            for (int i = 0; i < 16; ++i) acc[i] = 0ull;
            // h1(t-1) part first: needs no FULL wait
            gemm2<16, 64>(acc, wh, &sh[OFF_H1R + (1 - s) * 512 + e0 * 64]);
            BAR_SYNC(base + s);                      // FULL[s]: h0(t) ready
            gemm2<16, 64>(acc, wx, &sh[OFF_H0R + s * 512 + e0 * 64]);
            BAR_ARRIVE(base + 2 + s);                // EMPTY[s]: done reading h0(t)

#pragma unroll
            for (int e = 0; e < 4; ++e) {
                const float gi = sigf(foldadd(acc[e])      + bi);
                const float gf = sigf(foldadd(acc[4 + e])  + bf);
                const float gg = tanhe(foldadd(acc[8 + e]) + bg);
                const float go = sigf(foldadd(acc[12 + e]) + bo);
                c1[e] = fmaf(gf, c1[e], gi * gg);
                sh[OFF_H1R + s * 512 + (e0 + e) * 64 + j] = go * tanhe(c1[e]); // h1(t)
            }
            BAR_PAIR(base + 5);                      // L1 pair: h1(t) visible
        }
    }

    __syncthreads();

    // ---- FC head: out[b] = dot(Wfc, h1(335)[b]) + bfc ---- (slot 335&1 = 1)
    if (tid < 8) {
        const float* hv = &sh[OFF_H1R + 1 * 512 + tid * 64];
        float sum = 0.0f;
#pragma unroll 8
        for (int k = 0; k < 64; ++k) sum += Wfc[k] * hv[k];
        out[blockIdx.x * 8 + tid] = sum + bfc[0];
    }
}

extern "C" void kernel_launch(void* const* d_in, const int* in_sizes, int n_in,
                              void* d_out, int out_size)
{
    const float* x    = (const float*)d_in[0];
    const float* Wih0 = (const float*)d_in[1];
    const float* Whh0 = (const float*)d_in[2];
    const float* bih0 = (const float*)d_in[3];
    const float* bhh0 = (const float*)d_in[4];
    const float* Wih1 = (const float*)d_in[5];
    const float* Whh1 = (const float*)d_in[6];
    const float* bih1 = (const float*)d_in[7];
    const float* bhh1 = (const float*)d_in[8];
    const float* Wfc  = (const float*)d_in[9];
    const float* bfc  = (const float*)d_in[10];
    float* out = (float*)d_out;

    cudaFuncSetAttribute(lstm2_kernel,
                         cudaFuncAttributeMaxDynamicSharedMemorySize, SMEM_BYTES);
    lstm2_kernel<<<NCTAS, NT, SMEM_BYTES>>>(
        x, Wih0, Whh0, bih0, bhh0, Wih1, Whh1, bih1, bhh1, Wfc, bfc, out);
}

// round 17
// speedup vs baseline: 4.2163x; 4.2163x over previous
#include <cuda_runtime.h>
#include <cuda_fp16.h>
#include <cstddef>

// Fixed shapes
#define T_STEPS 336
#define NT      256          // 8 warps; warp w owns j = 8w..8w+7 for BOTH layers
#define NCTAS   128          // 8 batch elems per CTA
#define RSH     72           // halves per h/x row (pad: bank = q + 4r, conflict-free)

__device__ __forceinline__ float sigf(float x) {
    return __fdividef(1.0f, 1.0f + __expf(-x));
}
__device__ __forceinline__ float tanhe(float x) {
    return 1.0f - __fdividef(2.0f, __expf(2.0f * x) + 1.0f);
}

// D += A*B, m16n8k16, fp16 inputs, fp32 accum (HMMA)
__device__ __forceinline__ void mma16816(float* d, const unsigned* a, const unsigned* b) {
    asm volatile(
        "mma.sync.aligned.m16n8k16.row.col.f32.f16.f16.f32 "
        "{%0,%1,%2,%3},{%4,%5,%6,%7},{%8,%9},{%0,%1,%2,%3};"
        : "+f"(d[0]), "+f"(d[1]), "+f"(d[2]), "+f"(d[3])
        : "r"(a[0]), "r"(a[1]), "r"(a[2]), "r"(a[3]), "r"(b[0]), "r"(b[1]));
}

// B fragment: b0 = (k=2q,2q+1 ; n=r), b1 = (k+8 ; n=r). base = &hsm[r*RSH + 2q] (+kt*16)
__device__ __forceinline__ void ldb(unsigned* b, const __half* base) {
    b[0] = *reinterpret_cast<const unsigned*>(base);
    b[1] = *reinterpret_cast<const unsigned*>(base + 8);
}

// gmem fp32 pair -> packed fp16x2
__device__ __forceinline__ unsigned ldw(const float* W, int row, int col, int K) {
    const __half2 h = __floats2half2_rn(W[row * K + col], W[row * K + col + 1]);
    return *reinterpret_cast<const unsigned*>(&h);
}

__global__ void __launch_bounds__(NT, 1)
lstm2_kernel(const float* __restrict__ x,
             const float* __restrict__ Wih0, const float* __restrict__ Whh0,
             const float* __restrict__ bih0, const float* __restrict__ bhh0,
             const float* __restrict__ Wih1, const float* __restrict__ Whh1,
             const float* __restrict__ bih1, const float* __restrict__ bhh1,
             const float* __restrict__ Wfc,  const float* __restrict__ bfc,
             float* __restrict__ out)
{
    __shared__ __half xsm[8 * RSH];          // x(t), single buffer
    __shared__ __half h0sm[2 * 8 * RSH];     // h0 double buffer
    __shared__ __half h1sm[2 * 8 * RSH];     // h1 double buffer

    const int tid = threadIdx.x, wid = tid >> 5, lane = tid & 31;
    const int r = lane >> 2, q = lane & 3;
    const int j = wid * 8 + r;               // this lane's hidden index (rows r, r+8 of tiles)

    // ---- A fragments in registers (fp16x2). Tile rows: [i_j | f_j] and [g_j | o_j]. ----
    unsigned w0x_if[4], w0x_go[4];
    unsigned w0h_if[16], w0h_go[16], w1x_if[16], w1x_go[16], w1h_if[16], w1h_go[16];
    {
        const int c0 = 2 * q;
        w0x_if[0] = ldw(Wih0,       j, c0,     16);
        w0x_if[1] = ldw(Wih0,  64 + j, c0,     16);
        w0x_if[2] = ldw(Wih0,       j, c0 + 8, 16);
        w0x_if[3] = ldw(Wih0,  64 + j, c0 + 8, 16);
        w0x_go[0] = ldw(Wih0, 128 + j, c0,     16);
        w0x_go[1] = ldw(Wih0, 192 + j, c0,     16);
        w0x_go[2] = ldw(Wih0, 128 + j, c0 + 8, 16);
        w0x_go[3] = ldw(Wih0, 192 + j, c0 + 8, 16);
    }
#pragma unroll
    for (int kt = 0; kt < 4; ++kt) {
        const int c0 = kt * 16 + 2 * q;
        w0h_if[kt * 4 + 0] = ldw(Whh0,       j, c0,     64);
        w0h_if[kt * 4 + 1] = ldw(Whh0,  64 + j, c0,     64);
        w0h_if[kt * 4 + 2] = ldw(Whh0,       j, c0 + 8, 64);
        w0h_if[kt * 4 + 3] = ldw(Whh0,  64 + j, c0 + 8, 64);
        w0h_go[kt * 4 + 0] = ldw(Whh0, 128 + j, c0,     64);
        w0h_go[kt * 4 + 1] = ldw(Whh0, 192 + j, c0,     64);
        w0h_go[kt * 4 + 2] = ldw(Whh0, 128 + j, c0 + 8, 64);
        w0h_go[kt * 4 + 3] = ldw(Whh0, 192 + j, c0 + 8, 64);
        w1x_if[kt * 4 + 0] = ldw(Wih1,       j, c0,     64);
        w1x_if[kt * 4 + 1] = ldw(Wih1,  64 + j, c0,     64);
        w1x_if[kt * 4 + 2] = ldw(Wih1,       j, c0 + 8, 64);
        w1x_if[kt * 4 + 3] = ldw(Wih1,  64 + j, c0 + 8, 64);
        w1x_go[kt * 4 + 0] = ldw(Wih1, 128 + j, c0,     64);
        w1x_go[kt * 4 + 1] = ldw(Wih1, 192 + j, c0,     64);
        w1x_go[kt * 4 + 2] = ldw(Wih1, 128 + j, c0 + 8, 64);
        w1x_go[kt * 4 + 3] = ldw(Wih1, 192 + j, c0 + 8, 64);
        w1h_if[kt * 4 + 0] = ldw(Whh1,       j, c0,     64);
        w1h_if[kt * 4 + 1] = ldw(Whh1,  64 + j, c0,     64);
        w1h_if[kt * 4 + 2] = ldw(Whh1,       j, c0 + 8, 64);
        w1h_if[kt * 4 + 3] = ldw(Whh1,  64 + j, c0 + 8, 64);
        w1h_go[kt * 4 + 0] = ldw(Whh1, 128 + j, c0,     64);
        w1h_go[kt * 4 + 1] = ldw(Whh1, 192 + j, c0,     64);
        w1h_go[kt * 4 + 2] = ldw(Whh1, 128 + j, c0 + 8, 64);
        w1h_go[kt * 4 + 3] = ldw(Whh1, 192 + j, c0 + 8, 64);
    }

    // combined biases for this lane's j (baked into D accumulator init)
    const float b0i = bih0[j] + bhh0[j],             b0f = bih0[64 + j] + bhh0[64 + j];
    const float b0g = bih0[128 + j] + bhh0[128 + j], b0o = bih0[192 + j] + bhh0[192 + j];
    const float b1i = bih1[j] + bhh1[j],             b1f = bih1[64 + j] + bhh1[64 + j];
    const float b1g = bih1[128 + j] + bhh1[128 + j], b1o = bih1[192 + j] + bhh1[192 + j];

    // zero h rings
    for (int i = tid; i < 2 * 8 * RSH; i += NT) {
        h0sm[i] = __float2half(0.0f);
        h1sm[i] = __float2half(0.0f);
    }

    // x staging: warps 0-1 (64 lanes) -> (elem, k-pair)
    const float* xp = nullptr;
    float2 xv = make_float2(0.f, 0.f);
    int xe = 0, xkp = 0;
    if (wid < 2) {
        const int idx = wid * 32 + lane;
        xe = idx >> 3; xkp = idx & 7;
        xp = x + (size_t)(blockIdx.x * 8 + xe) * T_STEPS * 16 + 2 * xkp;
        const float2 x0 = *reinterpret_cast<const float2*>(xp);
        *reinterpret_cast<__half2*>(&xsm[xe * RSH + 2 * xkp]) = __floats2half2_rn(x0.x, x0.y);
        xv = *reinterpret_cast<const float2*>(xp + 16);    // x(1)
    }
    __syncthreads();

    float c0e[2] = {0.f, 0.f};   // cell state for (j, e=2q) and (j, e=2q+1)
    float c1e[2] = {0.f, 0.f};
    const __half* const myxb = &xsm[r * RSH + 2 * q];

    for (int t = 0; t < T_STEPS; ++t) {
        const int s = t & 1;

        // ================= Phase A: layer 0 =================
        float dif[4] = {b0i, b0i, b0f, b0f};
        float dgo[4] = {b0g, b0g, b0o, b0o};
        unsigned b[2];
        ldb(b, myxb);                                          // x(t)
        mma16816(dif, w0x_if, b);
        mma16816(dgo, w0x_go, b);
        const __half* hb = &h0sm[(1 - s) * 8 * RSH + r * RSH + 2 * q];   // h0(t-1)
#pragma unroll
        for (int kt = 0; kt < 4; ++kt) {
            ldb(b, hb + kt * 16);
            mma16816(dif, &w0h_if[kt * 4], b);
            mma16816(dgo, &w0h_go[kt * 4], b);
        }
        {
            __half* hw = &h0sm[s * 8 * RSH + j];
#pragma unroll
            for (int u = 0; u < 2; ++u) {
                const float gi = sigf(dif[u]);
                const float gf = sigf(dif[2 + u]);
                const float gg = tanhe(dgo[u]);
                const float go_ = sigf(dgo[2 + u]);
                c0e[u] = fmaf(gf, c0e[u], gi * gg);
                hw[(2 * q + u) * RSH] = __float2half(go_ * tanhe(c0e[u]));   // h0(t)
            }
        }
        __syncthreads();   // h0(t) visible to all warps

        // ================= Phase B: layer 1 =================
        float eif[4] = {b1i, b1i, b1f, b1f};
        float ego[4] = {b1g, b1g, b1o, b1o};
        const __half* h0b = &h0sm[s * 8 * RSH + r * RSH + 2 * q];        // h0(t)
        const __half* h1b = &h1sm[(1 - s) * 8 * RSH + r * RSH + 2 * q];  // h1(t-1)
#pragma unroll
        for (int kt = 0; kt < 4; ++kt) {
            ldb(b, h0b + kt * 16);
            mma16816(eif, &w1x_if[kt * 4], b);
            mma16816(ego, &w1x_go[kt * 4], b);
        }
#pragma unroll
        for (int kt = 0; kt < 4; ++kt) {
            ldb(b, h1b + kt * 16);
            mma16816(eif, &w1h_if[kt * 4], b);
            mma16816(ego, &w1h_go[kt * 4], b);
        }
        {
            __half* hw = &h1sm[s * 8 * RSH + j];
#pragma unroll
            for (int u = 0; u < 2; ++u) {
                const float gi = sigf(eif[u]);
                const float gf = sigf(eif[2 + u]);
                const float gg = tanhe(ego[u]);
                const float go_ = sigf(ego[2 + u]);
                c1e[u] = fmaf(gf, c1e[u], gi * gg);
                hw[(2 * q + u) * RSH] = __float2half(go_ * tanhe(c1e[u]));   // h1(t)
            }
        }
        if (wid < 2) {
            if (t + 1 < T_STEPS)
                *reinterpret_cast<__half2*>(&xsm[xe * RSH + 2 * xkp]) =
                    __floats2half2_rn(xv.x, xv.y);                           // x(t+1)
            if (t + 2 < T_STEPS)
                xv = *reinterpret_cast<const float2*>(xp + (size_t)(t + 2) * 16);
        }
        __syncthreads();   // h1(t), x(t+1) visible
    }

    // ---- FC head: out[b] = dot(Wfc, h1(335)[b]) + bfc ---- (slot 335&1 = 1)
    if (tid < 8) {
        const __half* hv = &h1sm[1 * 8 * RSH + tid * RSH];
        float sum = 0.0f;
#pragma unroll 8
        for (int k = 0; k < 64; ++k) sum += Wfc[k] * __half2float(hv[k]);
        out[blockIdx.x * 8 + tid] = sum + bfc[0];
    }
}

extern "C" void kernel_launch(void* const* d_in, const int* in_sizes, int n_in,
                              void* d_out, int out_size)
{
    const float* x    = (const float*)d_in[0];
    const float* Wih0 = (const float*)d_in[1];
    const float* Whh0 = (const float*)d_in[2];
    const float* bih0 = (const float*)d_in[3];
    const float* bhh0 = (const float*)d_in[4];
    const float* Wih1 = (const float*)d_in[5];
    const float* Whh1 = (const float*)d_in[6];
    const float* bih1 = (const float*)d_in[7];
    const float* bhh1 = (const float*)d_in[8];
    const float* Wfc  = (const float*)d_in[9];
    const float* bfc  = (const float*)d_in[10];
    float* out = (float*)d_out;

    lstm2_kernel<<<NCTAS, NT>>>(
        x, Wih0, Whh0, bih0, bhh0, Wih1, Whh1, bih1, bhh1, Wfc, bfc, out);
}